// round 16
// baseline (speedup 1.0000x reference)
#include <cuda_runtime.h>
#include <cuda_bf16.h>
#include <cstddef>
#include <cstdint>

#define NN 50000
#define NE 800000
#define NG 64
#define NB 196   // ceil(NN/256)

// ---------------- scratch (__device__ globals; no allocation allowed) ----------------
__device__ __align__(16) float d_x0[NN * 64];
__device__ __align__(16) float d_bufA[NN * 128];
__device__ __align__(16) float d_bufB[NN * 128];
__device__ __align__(16) float d_bufC[NN * 128];
__device__ __align__(16) float d_bufD[NN * 128];
__device__ __align__(16) float d_dinv[NN];
__device__ int d_ecnt[NN];
__device__ int d_cursor[NN];
__device__ int d_rowptr[NN + 1];
__device__ int d_bsum[256];
__device__ int d_boff[256];
__device__ int d_csr_src[NE];
__device__ int d_csr_dst[NE];
__device__ __align__(16) float d_csr_norm[NE];
__device__ __align__(16) float d_gmax[NG * 128];
__device__ __align__(16) float d_gsum[NG * 128];
__device__ float d_gcnt[NG];
__device__ __align__(16) float d_g[NG * 256];
__device__ __align__(16) float d_h1[NG * 256];
__device__ __align__(16) __nv_bfloat16 d_Whi[128 * 136];
__device__ __align__(16) __nv_bfloat16 d_Wlo[128 * 136];
__device__ __align__(16) __nv_bfloat16 d_gWhi[5 * 128 * 136];
__device__ __align__(16) __nv_bfloat16 d_gWlo[5 * 128 * 136];

#define WIMG (128 * 136)

// ---------------- mma.sync helpers ----------------
__device__ __forceinline__ uint32_t smem_u32(const void* p) {
    uint32_t a;
    asm("{ .reg .u64 t; cvta.to.shared.u64 t, %1; cvt.u32.u64 %0, t; }" : "=r"(a) : "l"(p));
    return a;
}
__device__ __forceinline__ void ldm_x4(uint32_t* r, uint32_t addr) {
    asm volatile("ldmatrix.sync.aligned.m8n8.x4.shared.b16 {%0,%1,%2,%3}, [%4];"
                 : "=r"(r[0]), "=r"(r[1]), "=r"(r[2]), "=r"(r[3]) : "r"(addr));
}
__device__ __forceinline__ void mma16816(float* d, const uint32_t* a, const uint32_t* b) {
    asm volatile("mma.sync.aligned.m16n8k16.row.col.f32.bf16.bf16.f32 "
                 "{%0,%1,%2,%3}, {%4,%5,%6,%7}, {%8,%9}, {%0,%1,%2,%3};"
                 : "+f"(d[0]), "+f"(d[1]), "+f"(d[2]), "+f"(d[3])
                 : "r"(a[0]), "r"(a[1]), "r"(a[2]), "r"(a[3]), "r"(b[0]), "r"(b[1]));
}
__device__ __forceinline__ void split_pack(float v0, float v1, uint32_t& hi, uint32_t& lo) {
    __nv_bfloat16 h0 = __float2bfloat16(v0), h1 = __float2bfloat16(v1);
    __nv_bfloat16 l0 = __float2bfloat16(v0 - __bfloat162float(h0));
    __nv_bfloat16 l1 = __float2bfloat16(v1 - __bfloat162float(h1));
    hi = (uint32_t)__bfloat16_as_ushort(h0) | ((uint32_t)__bfloat16_as_ushort(h1) << 16);
    lo = (uint32_t)__bfloat16_as_ushort(l0) | ((uint32_t)__bfloat16_as_ushort(l1) << 16);
}

// ---------------- graph preprocessing ----------------
__global__ void k_init() {
    int i = blockIdx.x * blockDim.x + threadIdx.x;
    if (i < NN) { d_ecnt[i] = 0; d_cursor[i] = 0; }
}

__global__ void k_count(const int* __restrict__ dst) {
    int e = blockIdx.x * blockDim.x + threadIdx.x;
    if (e < NE) atomicAdd(&d_ecnt[dst[e]], 1);
}

__global__ void k_bsum() {
    __shared__ int s[256];
    int t = threadIdx.x;
    int i = blockIdx.x * 256 + t;
    int c = (i < NN) ? d_ecnt[i] : 0;
    if (i < NN) d_dinv[i] = rsqrtf((float)c + 1.0f);
    s[t] = c;
    __syncthreads();
    #pragma unroll
    for (int off = 128; off > 0; off >>= 1) {
        if (t < off) s[t] += s[t + off];
        __syncthreads();
    }
    if (t == 0) d_bsum[blockIdx.x] = s[0];
}

__global__ void k_bscan() {
    __shared__ int s[256];
    int t = threadIdx.x;
    int v0 = (t < NB) ? d_bsum[t] : 0;
    s[t] = v0;
    __syncthreads();
    #pragma unroll
    for (int off = 1; off < 256; off <<= 1) {
        int v = (t >= off) ? s[t - off] : 0;
        __syncthreads();
        s[t] += v;
        __syncthreads();
    }
    d_boff[t] = s[t] - v0;
}

__global__ void k_escan() {
    __shared__ int s[256];
    int t = threadIdx.x;
    int i = blockIdx.x * 256 + t;
    int v0 = (i < NN) ? d_ecnt[i] : 0;
    s[t] = v0;
    __syncthreads();
    #pragma unroll
    for (int off = 1; off < 256; off <<= 1) {
        int v = (t >= off) ? s[t - off] : 0;
        __syncthreads();
        s[t] += v;
        __syncthreads();
    }
    if (i < NN) d_rowptr[i + 1] = d_boff[blockIdx.x] + s[t];
    if (i == 0) d_rowptr[0] = 0;
}

__global__ void k_scatter(const int* __restrict__ src, const int* __restrict__ dst) {
    int e = blockIdx.x * blockDim.x + threadIdx.x;
    if (e >= NE) return;
    int s = src[e], d = dst[e];
    int pos = d_rowptr[d] + atomicAdd(&d_cursor[d], 1);
    d_csr_src[pos] = s;
    d_csr_dst[pos] = d;
    d_csr_norm[pos] = d_dinv[s] * d_dinv[d];
}

// ---------------- x0 = [nodes | cat_emb[cats]] ----------------
__global__ void k_embed(const float* __restrict__ nodes, const int* __restrict__ cats,
                        const float* __restrict__ emb) {
    int t = blockIdx.x * blockDim.x + threadIdx.x;
    if (t >= NN * 16) return;
    int node = t >> 4, j = t & 15;
    float4 v;
    if (j < 8) v = ((const float4*)nodes)[node * 8 + j];
    else       v = ((const float4*)emb)[(size_t)cats[node] * 8 + (j - 8)];
    ((float4*)d_x0)[node * 16 + j] = v;
}

// ---------------- prebuild We2^T image + zero pool accumulators ----------------
__global__ void k_prepw(const float* __restrict__ We2) {
    int i = blockIdx.x * blockDim.x + threadIdx.x;
    if (i < NG * 128) { d_gmax[i] = 0.f; d_gsum[i] = 0.f; }
    if (i < NG) d_gcnt[i] = 0.f;
    if (i >= 16384) return;
    int n = i >> 7, k = i & 127;
    float w = We2[k * 128 + n];
    __nv_bfloat16 h = __float2bfloat16(w);
    __nv_bfloat16 l = __float2bfloat16(w - __bfloat162float(h));
    d_Whi[n * 136 + k] = h;
    d_Wlo[n * 136 + k] = l;
}

// ---------------- prebuild node-GEMM weight images ----------------
__global__ void k_prepw_gen(const float* __restrict__ W1, const float* __restrict__ W2,
                            const float* __restrict__ W3, const float* __restrict__ We1) {
    int i = blockIdx.x * blockDim.x + threadIdx.x;
    if (i >= 5 * 16384) return;
    int img = i >> 14;
    int idx = i & 16383;
    int n = idx >> 7, k = idx & 127;
    float w;
    if (img == 0) {
        if (k >= 64) return;
        w = W1[k * 128 + n];
    } else if (img == 1) {
        w = W2[k * 128 + n];
    } else if (img == 2) {
        w = W3[k * 128 + n];
    } else if (img == 3) {
        w = We1[k * 128 + n] - We1[(k + 128) * 128 + n];
    } else {
        w = We1[(k + 128) * 128 + n];
    }
    __nv_bfloat16 h = __float2bfloat16(w);
    __nv_bfloat16 l = __float2bfloat16(w - __bfloat162float(h));
    d_gWhi[img * WIMG + n * 136 + k] = h;
    d_gWlo[img * WIMG + n * 136 + k] = l;
}

// shared smem layout for 64-row MMA blocks
#define XHI 0u
#define XLO 17408u
#define WHI 34816u
#define WLO 69632u
#define MMA_SMEM 104448

// ---------------- fused CSR-agg gather into smem (bias+relu+split_pack) ----------------
// 4 threads per row (r = t&63, hf = t>>6 covers cols [hf*32, hf*32+32)).
__device__ __forceinline__ void gather_agg(const float* __restrict__ H, int M, int row0,
                                           const float* __restrict__ aggBias,
                                           char* smcBase, int t) {
    int r = t & 63, hf = t >> 6;
    int gr = row0 + r;
    char* pHi = smcBase + XHI;
    char* pLo = smcBase + XLO;
    uint32_t rowb = (uint32_t)r * 272u;
    if (gr < M) {
        float4 acc[8];
        const float4* Hr = (const float4*)(H + (size_t)gr * 128) + hf * 8;
        float dv = d_dinv[gr];
        float sn = dv * dv;
        #pragma unroll
        for (int s2 = 0; s2 < 8; ++s2) {
            float4 h = __ldg(Hr + s2);
            acc[s2] = make_float4(h.x * sn, h.y * sn, h.z * sn, h.w * sn);
        }
        int beg = d_rowptr[gr], end = d_rowptr[gr + 1];
        int e = beg;
        for (; e + 1 < end; e += 2) {
            int s0 = d_csr_src[e], s1 = d_csr_src[e + 1];
            float n0 = d_csr_norm[e], n1 = d_csr_norm[e + 1];
            const float4* H0 = (const float4*)(H + (size_t)s0 * 128) + hf * 8;
            const float4* H1 = (const float4*)(H + (size_t)s1 * 128) + hf * 8;
            #pragma unroll
            for (int s2 = 0; s2 < 8; ++s2) {
                float4 h0 = __ldg(H0 + s2);
                float4 h1 = __ldg(H1 + s2);
                acc[s2].x = fmaf(h0.x, n0, acc[s2].x); acc[s2].y = fmaf(h0.y, n0, acc[s2].y);
                acc[s2].z = fmaf(h0.z, n0, acc[s2].z); acc[s2].w = fmaf(h0.w, n0, acc[s2].w);
                acc[s2].x = fmaf(h1.x, n1, acc[s2].x); acc[s2].y = fmaf(h1.y, n1, acc[s2].y);
                acc[s2].z = fmaf(h1.z, n1, acc[s2].z); acc[s2].w = fmaf(h1.w, n1, acc[s2].w);
            }
        }
        if (e < end) {
            int s0 = d_csr_src[e];
            float n0 = d_csr_norm[e];
            const float4* H0 = (const float4*)(H + (size_t)s0 * 128) + hf * 8;
            #pragma unroll
            for (int s2 = 0; s2 < 8; ++s2) {
                float4 h0 = __ldg(H0 + s2);
                acc[s2].x = fmaf(h0.x, n0, acc[s2].x); acc[s2].y = fmaf(h0.y, n0, acc[s2].y);
                acc[s2].z = fmaf(h0.z, n0, acc[s2].z); acc[s2].w = fmaf(h0.w, n0, acc[s2].w);
            }
        }
        const float4* bb = (const float4*)aggBias + hf * 8;
        #pragma unroll
        for (int s2 = 0; s2 < 8; ++s2) {
            float4 b = __ldg(bb + s2);
            float v0 = fmaxf(acc[s2].x + b.x, 0.f);
            float v1 = fmaxf(acc[s2].y + b.y, 0.f);
            float v2 = fmaxf(acc[s2].z + b.z, 0.f);
            float v3 = fmaxf(acc[s2].w + b.w, 0.f);
            uint2 hv, lv;
            split_pack(v0, v1, hv.x, lv.x);
            split_pack(v2, v3, hv.y, lv.y);
            uint32_t off = rowb + (uint32_t)(hf * 8 + s2) * 8u;
            *(uint2*)(pHi + off) = hv;
            *(uint2*)(pLo + off) = lv;
        }
    } else {
        for (int s2 = 0; s2 < 8; ++s2) {
            uint32_t off = rowb + (uint32_t)(hf * 8 + s2) * 8u;
            *(uint2*)(pHi + off) = make_uint2(0u, 0u);
            *(uint2*)(pLo + off) = make_uint2(0u, 0u);
        }
    }
}

// ---------------- node GEMM via mma.sync bf16 3-split ----------------
// optional zeroPtr: zero this buffer's rows (for edge-agg output prep)
__global__ void __launch_bounds__(256, 2)
gemm_mma(const float* __restrict__ X, int M, int Kin,
         const __nv_bfloat16* __restrict__ gWhi, const __nv_bfloat16* __restrict__ gWlo,
         const float* __restrict__ bias, int doRelu, float* __restrict__ Y,
         float* __restrict__ zeroPtr) {
    extern __shared__ __align__(16) char smc[];
    const int t = threadIdx.x;
    const int wid = t >> 5;
    const int lane = t & 31;
    const int row0 = blockIdx.x * 64;
    const uint32_t sb = smem_u32(smc);

    {
        const uint4* gh = (const uint4*)gWhi;
        const uint4* gl = (const uint4*)gWlo;
        for (int i = t; i < 2176; i += 256) {
            asm volatile("cp.async.cg.shared.global [%0], [%1], 16;"
                         :: "r"(sb + WHI + i * 16), "l"(gh + i));
            asm volatile("cp.async.cg.shared.global [%0], [%1], 16;"
                         :: "r"(sb + WLO + i * 16), "l"(gl + i));
        }
        asm volatile("cp.async.commit_group;");
    }

    {
        int r = t & 63, hf = t >> 6;
        int gr = row0 + r;
        const float4* Xr = (const float4*)(X + (size_t)gr * Kin);
        int q = Kin >> 4;
        char* pHi = smc + XHI;
        char* pLo = smc + XLO;
        uint32_t rowb = (uint32_t)r * 272u;
        if (gr < M) {
            #pragma unroll 4
            for (int s = hf * q; s < (hf + 1) * q; ++s) {
                float4 v = __ldg(Xr + s);
                uint2 hv, lv;
                split_pack(v.x, v.y, hv.x, lv.x);
                split_pack(v.z, v.w, hv.y, lv.y);
                uint32_t off = rowb + (uint32_t)s * 8u;
                *(uint2*)(pHi + off) = hv;
                *(uint2*)(pLo + off) = lv;
            }
            if (zeroPtr) {
                float4* Z = (float4*)(zeroPtr + (size_t)gr * 128) + hf * 8;
                #pragma unroll
                for (int s2 = 0; s2 < 8; ++s2) Z[s2] = make_float4(0.f, 0.f, 0.f, 0.f);
            }
        } else {
            for (int s = hf * q; s < (hf + 1) * q; ++s) {
                uint32_t off = rowb + (uint32_t)s * 8u;
                *(uint2*)(pHi + off) = make_uint2(0u, 0u);
                *(uint2*)(pLo + off) = make_uint2(0u, 0u);
            }
        }
    }
    asm volatile("cp.async.wait_group 0;" ::: "memory");
    __syncthreads();

    const int wm = (wid & 1) * 32;
    const int wn = (wid >> 1) * 32;
    const int lid8 = lane & 7;
    const int grp = lane >> 3;

    uint32_t aAddrHi[2], aAddrLo[2];
    {
        uint32_t row = (uint32_t)(wm + (grp & 1) * 8 + lid8);
        uint32_t col = (uint32_t)((grp >> 1) * 8);
        #pragma unroll
        for (int mt = 0; mt < 2; ++mt) {
            uint32_t byteOff = (row + mt * 16) * 272u + col * 2u;
            aAddrHi[mt] = sb + XHI + byteOff;
            aAddrLo[mt] = sb + XLO + byteOff;
        }
    }
    uint32_t bAddrHi[2], bAddrLo[2];
    {
        uint32_t row = (uint32_t)(wn + (grp >> 1) * 8 + lid8);
        uint32_t col = (uint32_t)((grp & 1) * 8);
        #pragma unroll
        for (int p = 0; p < 2; ++p) {
            uint32_t byteOff = (row + p * 16) * 272u + col * 2u;
            bAddrHi[p] = sb + WHI + byteOff;
            bAddrLo[p] = sb + WLO + byteOff;
        }
    }

    float ac[2][4][4];
    #pragma unroll
    for (int i = 0; i < 2; i++)
        #pragma unroll
        for (int j = 0; j < 4; j++)
            #pragma unroll
            for (int q2 = 0; q2 < 4; q2++) ac[i][j][q2] = 0.f;

    const int nkt = Kin >> 4;
    for (int kt = 0; kt < nkt; ++kt) {
        uint32_t kb = kt * 32u;
        uint32_t aHi[2][4], aLo[2][4];
        uint32_t bHi[4][2], bLo[4][2];
        #pragma unroll
        for (int mt = 0; mt < 2; ++mt) {
            ldm_x4(aHi[mt], aAddrHi[mt] + kb);
            ldm_x4(aLo[mt], aAddrLo[mt] + kb);
        }
        #pragma unroll
        for (int p = 0; p < 2; ++p) {
            uint32_t r[4];
            ldm_x4(r, bAddrHi[p] + kb);
            bHi[2 * p][0] = r[0]; bHi[2 * p][1] = r[1];
            bHi[2 * p + 1][0] = r[2]; bHi[2 * p + 1][1] = r[3];
            ldm_x4(r, bAddrLo[p] + kb);
            bLo[2 * p][0] = r[0]; bLo[2 * p][1] = r[1];
            bLo[2 * p + 1][0] = r[2]; bLo[2 * p + 1][1] = r[3];
        }
        #pragma unroll
        for (int mt = 0; mt < 2; ++mt)
            #pragma unroll
            for (int nt = 0; nt < 4; ++nt) {
                mma16816(ac[mt][nt], aHi[mt], bHi[nt]);
                mma16816(ac[mt][nt], aHi[mt], bLo[nt]);
                mma16816(ac[mt][nt], aLo[mt], bHi[nt]);
            }
    }

    {
        int rr = lane >> 2;
        int cc = (lane & 3) * 2;
        #pragma unroll
        for (int nt = 0; nt < 4; ++nt) {
            int c = wn + nt * 8 + cc;
            float b0 = bias ? __ldg(bias + c)     : 0.f;
            float b1 = bias ? __ldg(bias + c + 1) : 0.f;
            #pragma unroll
            for (int mt = 0; mt < 2; ++mt) {
                int r0 = wm + mt * 16 + rr;
                int gr0 = row0 + r0;
                int gr1 = gr0 + 8;
                float o00 = ac[mt][nt][0] + b0, o01 = ac[mt][nt][1] + b1;
                float o10 = ac[mt][nt][2] + b0, o11 = ac[mt][nt][3] + b1;
                if (doRelu) {
                    o00 = fmaxf(o00, 0.f); o01 = fmaxf(o01, 0.f);
                    o10 = fmaxf(o10, 0.f); o11 = fmaxf(o11, 0.f);
                }
                if (gr0 < M)
                    *(float2*)&Y[(size_t)gr0 * 128 + c] = make_float2(o00, o01);
                if (gr1 < M)
                    *(float2*)&Y[(size_t)gr1 * 128 + c] = make_float2(o10, o11);
            }
        }
    }
}

// ---------------- GEMM with fused CSR-agg gather: Y = relu(agg(H)+aggBias) @ W ----------------
__global__ void __launch_bounds__(256, 2)
gemm_mma_agg(const float* __restrict__ H, int M,
             const float* __restrict__ aggBias,
             const __nv_bfloat16* __restrict__ gWhi, const __nv_bfloat16* __restrict__ gWlo,
             float* __restrict__ Y) {
    extern __shared__ __align__(16) char smc[];
    const int t = threadIdx.x;
    const int wid = t >> 5;
    const int lane = t & 31;
    const int row0 = blockIdx.x * 64;
    const uint32_t sb = smem_u32(smc);

    {
        const uint4* gh = (const uint4*)gWhi;
        const uint4* gl = (const uint4*)gWlo;
        for (int i = t; i < 2176; i += 256) {
            asm volatile("cp.async.cg.shared.global [%0], [%1], 16;"
                         :: "r"(sb + WHI + i * 16), "l"(gh + i));
            asm volatile("cp.async.cg.shared.global [%0], [%1], 16;"
                         :: "r"(sb + WLO + i * 16), "l"(gl + i));
        }
        asm volatile("cp.async.commit_group;");
    }

    gather_agg(H, M, row0, aggBias, smc, t);

    asm volatile("cp.async.wait_group 0;" ::: "memory");
    __syncthreads();

    const int wm = (wid & 1) * 32;
    const int wn = (wid >> 1) * 32;
    const int lid8 = lane & 7;
    const int grp = lane >> 3;

    uint32_t aAddrHi[2], aAddrLo[2];
    {
        uint32_t row = (uint32_t)(wm + (grp & 1) * 8 + lid8);
        uint32_t col = (uint32_t)((grp >> 1) * 8);
        #pragma unroll
        for (int mt = 0; mt < 2; ++mt) {
            uint32_t byteOff = (row + mt * 16) * 272u + col * 2u;
            aAddrHi[mt] = sb + XHI + byteOff;
            aAddrLo[mt] = sb + XLO + byteOff;
        }
    }
    uint32_t bAddrHi[2], bAddrLo[2];
    {
        uint32_t row = (uint32_t)(wn + (grp >> 1) * 8 + lid8);
        uint32_t col = (uint32_t)((grp & 1) * 8);
        #pragma unroll
        for (int p = 0; p < 2; ++p) {
            uint32_t byteOff = (row + p * 16) * 272u + col * 2u;
            bAddrHi[p] = sb + WHI + byteOff;
            bAddrLo[p] = sb + WLO + byteOff;
        }
    }

    float ac[2][4][4];
    #pragma unroll
    for (int i = 0; i < 2; i++)
        #pragma unroll
        for (int j = 0; j < 4; j++)
            #pragma unroll
            for (int q2 = 0; q2 < 4; q2++) ac[i][j][q2] = 0.f;

    #pragma unroll
    for (int kt = 0; kt < 8; ++kt) {
        uint32_t kb = kt * 32u;
        uint32_t aHi[2][4], aLo[2][4];
        uint32_t bHi[4][2], bLo[4][2];
        #pragma unroll
        for (int mt = 0; mt < 2; ++mt) {
            ldm_x4(aHi[mt], aAddrHi[mt] + kb);
            ldm_x4(aLo[mt], aAddrLo[mt] + kb);
        }
        #pragma unroll
        for (int p = 0; p < 2; ++p) {
            uint32_t r[4];
            ldm_x4(r, bAddrHi[p] + kb);
            bHi[2 * p][0] = r[0]; bHi[2 * p][1] = r[1];
            bHi[2 * p + 1][0] = r[2]; bHi[2 * p + 1][1] = r[3];
            ldm_x4(r, bAddrLo[p] + kb);
            bLo[2 * p][0] = r[0]; bLo[2 * p][1] = r[1];
            bLo[2 * p + 1][0] = r[2]; bLo[2 * p + 1][1] = r[3];
        }
        #pragma unroll
        for (int mt = 0; mt < 2; ++mt)
            #pragma unroll
            for (int nt = 0; nt < 4; ++nt) {
                mma16816(ac[mt][nt], aHi[mt], bHi[nt]);
                mma16816(ac[mt][nt], aHi[mt], bLo[nt]);
                mma16816(ac[mt][nt], aLo[mt], bHi[nt]);
            }
    }

    {
        int rr = lane >> 2;
        int cc = (lane & 3) * 2;
        #pragma unroll
        for (int nt = 0; nt < 4; ++nt) {
            int c = wn + nt * 8 + cc;
            #pragma unroll
            for (int mt = 0; mt < 2; ++mt) {
                int r0 = wm + mt * 16 + rr;
                int gr0 = row0 + r0;
                int gr1 = gr0 + 8;
                if (gr0 < M)
                    *(float2*)&Y[(size_t)gr0 * 128 + c] = make_float2(ac[mt][nt][0], ac[mt][nt][1]);
                if (gr1 < M)
                    *(float2*)&Y[(size_t)gr1 * 128 + c] = make_float2(ac[mt][nt][2], ac[mt][nt][3]);
            }
        }
    }
}

// ---------------- fused dual GEMM with agg gather: x3 = relu(agg(H)+b3); A=x3@Wd+be1; B=x3@Wb ----------------
__global__ void __launch_bounds__(256, 2)
gemm_mma_dual_agg(const float* __restrict__ H, int M,
                  const float* __restrict__ aggBias,
                  const __nv_bfloat16* __restrict__ WdHi, const __nv_bfloat16* __restrict__ WdLo,
                  const __nv_bfloat16* __restrict__ WbHi, const __nv_bfloat16* __restrict__ WbLo,
                  const float* __restrict__ be1,
                  float* __restrict__ Aout, float* __restrict__ Bout) {
    extern __shared__ __align__(16) char smc[];
    const int t = threadIdx.x;
    const int wid = t >> 5;
    const int lane = t & 31;
    const int row0 = blockIdx.x * 64;
    const uint32_t sb = smem_u32(smc);

    {
        const uint4* gh = (const uint4*)WdHi;
        const uint4* gl = (const uint4*)WdLo;
        for (int i = t; i < 2176; i += 256) {
            asm volatile("cp.async.cg.shared.global [%0], [%1], 16;"
                         :: "r"(sb + WHI + i * 16), "l"(gh + i));
            asm volatile("cp.async.cg.shared.global [%0], [%1], 16;"
                         :: "r"(sb + WLO + i * 16), "l"(gl + i));
        }
        asm volatile("cp.async.commit_group;");
    }

    gather_agg(H, M, row0, aggBias, smc, t);

    asm volatile("cp.async.wait_group 0;" ::: "memory");
    __syncthreads();

    const int wm = (wid & 1) * 32;
    const int wn = (wid >> 1) * 32;
    const int lid8 = lane & 7;
    const int grp = lane >> 3;

    uint32_t aAddrHi[2], aAddrLo[2];
    {
        uint32_t row = (uint32_t)(wm + (grp & 1) * 8 + lid8);
        uint32_t col = (uint32_t)((grp >> 1) * 8);
        #pragma unroll
        for (int mt = 0; mt < 2; ++mt) {
            uint32_t byteOff = (row + mt * 16) * 272u + col * 2u;
            aAddrHi[mt] = sb + XHI + byteOff;
            aAddrLo[mt] = sb + XLO + byteOff;
        }
    }
    uint32_t bAddrHi[2], bAddrLo[2];
    {
        uint32_t row = (uint32_t)(wn + (grp >> 1) * 8 + lid8);
        uint32_t col = (uint32_t)((grp & 1) * 8);
        #pragma unroll
        for (int p = 0; p < 2; ++p) {
            uint32_t byteOff = (row + p * 16) * 272u + col * 2u;
            bAddrHi[p] = sb + WHI + byteOff;
            bAddrLo[p] = sb + WLO + byteOff;
        }
    }

    const int rr = lane >> 2;
    const int cc = (lane & 3) * 2;

    #pragma unroll 1
    for (int pass = 0; pass < 2; ++pass) {
        float ac[2][4][4];
        #pragma unroll
        for (int i = 0; i < 2; i++)
            #pragma unroll
            for (int j = 0; j < 4; j++)
                #pragma unroll
                for (int q2 = 0; q2 < 4; q2++) ac[i][j][q2] = 0.f;

        #pragma unroll
        for (int kt = 0; kt < 8; ++kt) {
            uint32_t kb = kt * 32u;
            uint32_t aHi[2][4], aLo[2][4];
            uint32_t bHi[4][2], bLo[4][2];
            #pragma unroll
            for (int mt = 0; mt < 2; ++mt) {
                ldm_x4(aHi[mt], aAddrHi[mt] + kb);
                ldm_x4(aLo[mt], aAddrLo[mt] + kb);
            }
            #pragma unroll
            for (int p = 0; p < 2; ++p) {
                uint32_t r[4];
                ldm_x4(r, bAddrHi[p] + kb);
                bHi[2 * p][0] = r[0]; bHi[2 * p][1] = r[1];
                bHi[2 * p + 1][0] = r[2]; bHi[2 * p + 1][1] = r[3];
                ldm_x4(r, bAddrLo[p] + kb);
                bLo[2 * p][0] = r[0]; bLo[2 * p][1] = r[1];
                bLo[2 * p + 1][0] = r[2]; bLo[2 * p + 1][1] = r[3];
            }
            #pragma unroll
            for (int mt = 0; mt < 2; ++mt)
                #pragma unroll
                for (int nt = 0; nt < 4; ++nt) {
                    mma16816(ac[mt][nt], aHi[mt], bHi[nt]);
                    mma16816(ac[mt][nt], aHi[mt], bLo[nt]);
                    mma16816(ac[mt][nt], aLo[mt], bHi[nt]);
                }
        }

        if (pass == 0) {
            __syncthreads();
            {
                const uint4* gh = (const uint4*)WbHi;
                const uint4* gl = (const uint4*)WbLo;
                for (int i = t; i < 2176; i += 256) {
                    asm volatile("cp.async.cg.shared.global [%0], [%1], 16;"
                                 :: "r"(sb + WHI + i * 16), "l"(gh + i));
                    asm volatile("cp.async.cg.shared.global [%0], [%1], 16;"
                                 :: "r"(sb + WLO + i * 16), "l"(gl + i));
                }
                asm volatile("cp.async.commit_group;");
            }
            #pragma unroll
            for (int nt = 0; nt < 4; ++nt) {
                int c = wn + nt * 8 + cc;
                float b0 = __ldg(be1 + c);
                float b1 = __ldg(be1 + c + 1);
                #pragma unroll
                for (int mt = 0; mt < 2; ++mt) {
                    int r0 = wm + mt * 16 + rr;
                    int gr0 = row0 + r0;
                    int gr1 = gr0 + 8;
                    if (gr0 < M)
                        *(float2*)&Aout[(size_t)gr0 * 128 + c] =
                            make_float2(ac[mt][nt][0] + b0, ac[mt][nt][1] + b1);
                    if (gr1 < M)
                        *(float2*)&Aout[(size_t)gr1 * 128 + c] =
                            make_float2(ac[mt][nt][2] + b0, ac[mt][nt][3] + b1);
                }
            }
            asm volatile("cp.async.wait_group 0;" ::: "memory");
            __syncthreads();
        } else {
            #pragma unroll
            for (int nt = 0; nt < 4; ++nt) {
                int c = wn + nt * 8 + cc;
                #pragma unroll
                for (int mt = 0; mt < 2; ++mt) {
                    int r0 = wm + mt * 16 + rr;
                    int gr0 = row0 + r0;
                    int gr1 = gr0 + 8;
                    if (gr0 < M)
                        *(float2*)&Bout[(size_t)gr0 * 128 + c] =
                            make_float2(ac[mt][nt][0], ac[mt][nt][1]);
                    if (gr1 < M)
                        *(float2*)&Bout[(size_t)gr1 * 128 + c] =
                            make_float2(ac[mt][nt][2], ac[mt][nt][3]);
                }
            }
        }
    }
}

// ---------------- GCN aggregation, 64 cols (layer-1 pre-agg) ----------------
__global__ void gcn_agg64(const float* __restrict__ H, float* __restrict__ out) {
    int t = threadIdx.x;
    int half = t >> 4;
    int li = t & 15;
    int node = blockIdx.x * 16 + half;
    if (node >= NN) return;
    float dv = d_dinv[node];
    float sn = dv * dv;
    float4 acc = ((const float4*)H)[node * 16 + li];
    acc.x *= sn; acc.y *= sn; acc.z *= sn; acc.w *= sn;
    int beg = d_rowptr[node], end = d_rowptr[node + 1];
    int e = beg;
    for (; e + 3 < end; e += 4) {
        int s0 = d_csr_src[e],     s1 = d_csr_src[e + 1];
        int s2 = d_csr_src[e + 2], s3 = d_csr_src[e + 3];
        float n0 = d_csr_norm[e],     n1 = d_csr_norm[e + 1];
        float n2 = d_csr_norm[e + 2], n3 = d_csr_norm[e + 3];
        float4 h0 = ((const float4*)H)[s0 * 16 + li];
        float4 h1 = ((const float4*)H)[s1 * 16 + li];
        float4 h2 = ((const float4*)H)[s2 * 16 + li];
        float4 h3 = ((const float4*)H)[s3 * 16 + li];
        acc.x = fmaf(h0.x, n0, acc.x); acc.y = fmaf(h0.y, n0, acc.y);
        acc.z = fmaf(h0.z, n0, acc.z); acc.w = fmaf(h0.w, n0, acc.w);
        acc.x = fmaf(h1.x, n1, acc.x); acc.y = fmaf(h1.y, n1, acc.y);
        acc.z = fmaf(h1.z, n1, acc.z); acc.w = fmaf(h1.w, n1, acc.w);
        acc.x = fmaf(h2.x, n2, acc.x); acc.y = fmaf(h2.y, n2, acc.y);
        acc.z = fmaf(h2.z, n2, acc.z); acc.w = fmaf(h2.w, n2, acc.w);
        acc.x = fmaf(h3.x, n3, acc.x); acc.y = fmaf(h3.y, n3, acc.y);
        acc.z = fmaf(h3.z, n3, acc.z); acc.w = fmaf(h3.w, n3, acc.w);
    }
    for (; e < end; ++e) {
        int s = d_csr_src[e];
        float nm = d_csr_norm[e];
        float4 h = ((const float4*)H)[s * 16 + li];
        acc.x = fmaf(h.x, nm, acc.x); acc.y = fmaf(h.y, nm, acc.y);
        acc.z = fmaf(h.z, nm, acc.z); acc.w = fmaf(h.w, nm, acc.w);
    }
    ((float4*)out)[node * 16 + li] = acc;
}

// ---------------- EdgeConv via mma.sync bf16 3-MMA split ----------------
__global__ void __launch_bounds__(256, 2)
edge_mlp_mma(const float* __restrict__ A, const float* __restrict__ Bm,
             const float* __restrict__ be2, float* __restrict__ agg) {
    extern __shared__ __align__(16) char smc[];
    __shared__ int sDst[64];
    __shared__ int sSrc[64];

    const int t = threadIdx.x;
    const int wid = t >> 5;
    const int lane = t & 31;
    const int e0 = blockIdx.x * 64;
    const uint32_t sb = smem_u32(smc);

    if (t < 64) { sDst[t] = d_csr_dst[e0 + t]; sSrc[t] = d_csr_src[e0 + t]; }

    {
        const uint4* gh = (const uint4*)d_Whi;
        const uint4* gl = (const uint4*)d_Wlo;
        for (int i = t; i < 2176; i += 256) {
            asm volatile("cp.async.cg.shared.global [%0], [%1], 16;"
                         :: "r"(sb + WHI + i * 16), "l"(gh + i));
            asm volatile("cp.async.cg.shared.global [%0], [%1], 16;"
                         :: "r"(sb + WLO + i * 16), "l"(gl + i));
        }
        asm volatile("cp.async.commit_group;");
    }
    __syncthreads();

    {
        int e = t & 63, hf = t >> 6;
        int d = sDst[e], s = sSrc[e];
        const float4* Ad = (const float4*)(A  + (size_t)d * 128);
        const float4* Bs = (const float4*)(Bm + (size_t)s * 128);
        uint32_t rowb = (uint32_t)e * 272u;
        char* pHi = smc + XHI;
        char* pLo = smc + XLO;
        #pragma unroll 8
        for (int seg = hf * 8; seg < hf * 8 + 8; ++seg) {
            float4 av = __ldg(Ad + seg);
            float4 bv = __ldg(Bs + seg);
            float v0 = fmaxf(av.x + bv.x, 0.f);
            float v1 = fmaxf(av.y + bv.y, 0.f);
            float v2 = fmaxf(av.z + bv.z, 0.f);
            float v3 = fmaxf(av.w + bv.w, 0.f);
            uint2 hv, lv;
            split_pack(v0, v1, hv.x, lv.x);
            split_pack(v2, v3, hv.y, lv.y);
            uint32_t off = rowb + (uint32_t)seg * 8u;
            *(uint2*)(pHi + off) = hv;
            *(uint2*)(pLo + off) = lv;
        }
    }
    asm volatile("cp.async.wait_group 0;" ::: "memory");
    __syncthreads();

    const int wm = (wid & 1) * 32;
    const int wn = (wid >> 1) * 32;
    const int lid8 = lane & 7;
    const int grp = lane >> 3;

    uint32_t aAddrHi[2], aAddrLo[2];
    {
        uint32_t row = (uint32_t)(wm + (grp & 1) * 8 + lid8);
        uint32_t col = (uint32_t)((grp >> 1) * 8);
        #pragma unroll
        for (int mt = 0; mt < 2; ++mt) {
            uint32_t byteOff = (row + mt * 16) * 272u + col * 2u;
            aAddrHi[mt] = sb + XHI + byteOff;
            aAddrLo[mt] = sb + XLO + byteOff;
        }
    }
    uint32_t bAddrHi[2], bAddrLo[2];
    {
        uint32_t row = (uint32_t)(wn + (grp >> 1) * 8 + lid8);
        uint32_t col = (uint32_t)((grp & 1) * 8);
        #pragma unroll
        for (int p = 0; p < 2; ++p) {
            uint32_t byteOff = (row + p * 16) * 272u + col * 2u;
            bAddrHi[p] = sb + WHI + byteOff;
            bAddrLo[p] = sb + WLO + byteOff;
        }
    }

    float ac[2][4][4];
    #pragma unroll
    for (int i = 0; i < 2; i++)
        #pragma unroll
        for (int j = 0; j < 4; j++)
            #pragma unroll
            for (int q2 = 0; q2 < 4; q2++) ac[i][j][q2] = 0.f;

    #pragma unroll
    for (int kt = 0; kt < 8; ++kt) {
        uint32_t kb = kt * 32u;
        uint32_t aHi[2][4], aLo[2][4];
        uint32_t bHi[4][2], bLo[4][2];
        #pragma unroll
        for (int mt = 0; mt < 2; ++mt) {
            ldm_x4(aHi[mt], aAddrHi[mt] + kb);
            ldm_x4(aLo[mt], aAddrLo[mt] + kb);
        }
        #pragma unroll
        for (int p = 0; p < 2; ++p) {
            uint32_t r[4];
            ldm_x4(r, bAddrHi[p] + kb);
            bHi[2 * p][0] = r[0]; bHi[2 * p][1] = r[1];
            bHi[2 * p + 1][0] = r[2]; bHi[2 * p + 1][1] = r[3];
            ldm_x4(r, bAddrLo[p] + kb);
            bLo[2 * p][0] = r[0]; bLo[2 * p][1] = r[1];
            bLo[2 * p + 1][0] = r[2]; bLo[2 * p + 1][1] = r[3];
        }
        #pragma unroll
        for (int mt = 0; mt < 2; ++mt)
            #pragma unroll
            for (int nt = 0; nt < 4; ++nt) {
                mma16816(ac[mt][nt], aHi[mt], bHi[nt]);
                mma16816(ac[mt][nt], aHi[mt], bLo[nt]);
                mma16816(ac[mt][nt], aLo[mt], bHi[nt]);
            }
    }
    __syncthreads();

    float* sR = (float*)smc;
    {
        int rr = lane >> 2;
        int cc = (lane & 3) * 2;
        #pragma unroll
        for (int mt = 0; mt < 2; ++mt)
            #pragma unroll
            for (int nt = 0; nt < 4; ++nt) {
                int r0 = wm + mt * 16 + rr;
                int c = wn + nt * 8 + cc;
                *(float2*)&sR[r0 * 130 + c]       = make_float2(ac[mt][nt][0], ac[mt][nt][1]);
                *(float2*)&sR[(r0 + 8) * 130 + c] = make_float2(ac[mt][nt][2], ac[mt][nt][3]);
            }
    }
    __syncthreads();

    {
        int col = t >> 1;
        int q = t & 1;
        int eb = q * 32;
        float bias = __ldg(be2 + col);
        int cur = sDst[eb];
        float m = sR[eb * 130 + col];
        #pragma unroll 4
        for (int i = 1; i < 32; ++i) {
            int e = eb + i;
            int d = sDst[e];
            float v = sR[e * 130 + col];
            if (d != cur) {
                float mb = m + bias;
                if (mb > 0.f) atomicMax((int*)(agg + (size_t)cur * 128 + col), __float_as_int(mb));
                cur = d; m = v;
            } else {
                m = fmaxf(m, v);
            }
        }
        float mb = m + bias;
        if (mb > 0.f) atomicMax((int*)(agg + (size_t)cur * 128 + col), __float_as_int(mb));
    }
}

// ---------------- pooling ----------------
__global__ void __launch_bounds__(256)
k_pool2(const int* __restrict__ batch, const float* __restrict__ X) {
    int base = blockIdx.x * 128;
    int ch = threadIdx.x & 127;
    int half = threadIdx.x >> 7;
    int cur = -1;
    float vmax = 0.f, vsum = 0.f;
    for (int i = half; i < 128; i += 2) {
        int n = base + i;
        if (n >= NN) break;
        int g = batch[n];
        if (g != cur) {
            if (cur >= 0) {
                atomicAdd(&d_gsum[cur * 128 + ch], vsum);
                if (vmax > 0.f) atomicMax((int*)&d_gmax[cur * 128 + ch], __float_as_int(vmax));
            }
            cur = g; vmax = 0.f; vsum = 0.f;
        }
        float v = X[(size_t)n * 128 + ch];
        vsum += v;
        vmax = fmaxf(vmax, v);
    }
    if (cur >= 0) {
        atomicAdd(&d_gsum[cur * 128 + ch], vsum);
        if (vmax > 0.f) atomicMax((int*)&d_gmax[cur * 128 + ch], __float_as_int(vmax));
    }
    if (threadIdx.x == 0) {
        int c = -1; float cnt = 0.f;
        for (int i = 0; i < 128; ++i) {
            int n = base + i;
            if (n >= NN) break;
            int g = batch[n];
            if (g != c) {
                if (c >= 0) atomicAdd(&d_gcnt[c], cnt);
                c = g; cnt = 0.f;
            }
            cnt += 1.f;
        }
        if (c >= 0) atomicAdd(&d_gcnt[c], cnt);
    }
}

__global__ void k_pool_fin() {
    int t = blockIdx.x * blockDim.x + threadIdx.x;
    if (t >= NG * 256) return;
    int g = t >> 8, c = t & 255;
    float v;
    if (c < 128) v = d_gmax[g * 128 + c];
    else         v = d_gsum[g * 128 + c - 128] / fmaxf(d_gcnt[g], 1.0f);
    d_g[t] = v;
}

// ---------------- head ----------------
__global__ void head_gemm(const float* __restrict__ in, const float* __restrict__ W,
                          const float* __restrict__ b, float* __restrict__ out) {
    __shared__ float srow[256];
    int t = threadIdx.x;
    int g = blockIdx.x;
    srow[t] = in[g * 256 + t];
    __syncthreads();
    float acc = b[t];
    #pragma unroll 8
    for (int k = 0; k < 256; ++k) acc = fmaf(srow[k], W[k * 256 + t], acc);
    out[g * 256 + t] = fmaxf(acc, 0.f);
}

// ---------------- launch ----------------
extern "C" void kernel_launch(void* const* d_in, const int* in_sizes, int n_in,
                              void* d_out, int out_size) {
    const float* nodes   = (const float*)d_in[0];
    const int*   cats    = (const int*)d_in[1];
    const int*   ei      = (const int*)d_in[2];
    const int*   batch   = (const int*)d_in[3];
    const float* cat_emb = (const float*)d_in[4];
    const float* W1  = (const float*)d_in[5];
    const float* b1  = (const float*)d_in[6];
    const float* W2  = (const float*)d_in[7];
    const float* b2  = (const float*)d_in[8];
    const float* W3  = (const float*)d_in[9];
    const float* b3  = (const float*)d_in[10];
    const float* We1 = (const float*)d_in[11];
    const float* be1 = (const float*)d_in[12];
    const float* We2 = (const float*)d_in[13];
    const float* be2 = (const float*)d_in[14];
    const float* Wf1 = (const float*)d_in[15];
    const float* bf1 = (const float*)d_in[16];
    const float* Wf2 = (const float*)d_in[17];
    const float* bf2 = (const float*)d_in[18];
    const int* src = ei;
    const int* dst = ei + NE;
    float* out = (float*)d_out;

    cudaFuncSetAttribute(gemm_mma,          cudaFuncAttributeMaxDynamicSharedMemorySize, MMA_SMEM);
    cudaFuncSetAttribute(gemm_mma_agg,      cudaFuncAttributeMaxDynamicSharedMemorySize, MMA_SMEM);
    cudaFuncSetAttribute(gemm_mma_dual_agg, cudaFuncAttributeMaxDynamicSharedMemorySize, MMA_SMEM);
    cudaFuncSetAttribute(edge_mlp_mma,      cudaFuncAttributeMaxDynamicSharedMemorySize, MMA_SMEM);

    float *bufA, *bufB, *bufC, *bufD, *x0, *g, *h1;
    __nv_bfloat16 *gwh, *gwl;
    cudaGetSymbolAddress((void**)&bufA, d_bufA);
    cudaGetSymbolAddress((void**)&bufB, d_bufB);
    cudaGetSymbolAddress((void**)&bufC, d_bufC);
    cudaGetSymbolAddress((void**)&bufD, d_bufD);
    cudaGetSymbolAddress((void**)&x0,   d_x0);
    cudaGetSymbolAddress((void**)&g,    d_g);
    cudaGetSymbolAddress((void**)&h1,   d_h1);
    cudaGetSymbolAddress((void**)&gwh,  d_gWhi);
    cudaGetSymbolAddress((void**)&gwl,  d_gWlo);

    // CSR + norms
    k_init<<<(NN + 255) / 256, 256>>>();
    k_count<<<(NE + 255) / 256, 256>>>(dst);
    k_bsum<<<NB, 256>>>();          // also computes dinv
    k_bscan<<<1, 256>>>();
    k_escan<<<NB, 256>>>();
    k_scatter<<<(NE + 255) / 256, 256>>>(src, dst);

    // x0 = [nodes | emb]; weight images (+ pool accumulator zeroing in k_prepw)
    k_embed<<<(NN * 16 + 255) / 256, 256>>>(nodes, cats, cat_emb);
    k_prepw<<<64, 256>>>(We2);
    k_prepw_gen<<<(5 * 16384 + 255) / 256, 256>>>(W1, W2, W3, We1);

    const int gg = (NN + 63) / 64;  // 782
    // GCN 1: pre-agg x0 (64-dim), then GEMM with bias+relu; also zeroes bufD
    gcn_agg64<<<(NN + 15) / 16, 256>>>(x0, bufC);
    gemm_mma<<<gg, 256, MMA_SMEM>>>(bufC, NN, 64, gwh + 0 * WIMG, gwl + 0 * WIMG, b1, 1, bufB, bufD);
    // GCN 2 GEMM: h2 = x1 @ W2  (agg fused into next kernel)
    gemm_mma<<<gg, 256, MMA_SMEM>>>(bufB, NN, 128, gwh + 1 * WIMG, gwl + 1 * WIMG, nullptr, 0, bufA, nullptr);
    // GCN 3 (fused agg of h2 w/ b2+relu -> x2; then @ W3): h3 -> bufB
    gemm_mma_agg<<<gg, 256, MMA_SMEM>>>(bufA, NN, b2, gwh + 2 * WIMG, gwl + 2 * WIMG, bufB);
    // EdgeConv precompute (fused agg of h3 w/ b3+relu -> x3; dual GEMM): A -> bufA, B -> bufC
    gemm_mma_dual_agg<<<gg, 256, MMA_SMEM>>>(bufB, NN, b3,
                                             gwh + 3 * WIMG, gwl + 3 * WIMG,
                                             gwh + 4 * WIMG, gwl + 4 * WIMG,
                                             be1, bufA, bufC);

    // EdgeConv per-edge MLP + segment max (bufD pre-zeroed by layer-1 GEMM)
    edge_mlp_mma<<<NE / 64, 256, MMA_SMEM>>>(bufA, bufC, be2, bufD);

    // pooling (accumulators pre-zeroed in k_prepw)
    k_pool2<<<(NN + 127) / 128, 256>>>(batch, bufD);
    k_pool_fin<<<(NG * 256 + 255) / 256, 256>>>();

    // head
    head_gemm<<<NG, 256>>>(g, Wf1, bf1, h1);
    head_gemm<<<NG, 256>>>(h1, Wf2, bf2, out);
}

// round 17
// speedup vs baseline: 1.2787x; 1.2787x over previous
#include <cuda_runtime.h>
#include <cuda_bf16.h>
#include <cstddef>
#include <cstdint>

#define NN 50000
#define NE 800000
#define NG 64
#define NB 196   // ceil(NN/256)

// ---------------- scratch (__device__ globals; no allocation allowed) ----------------
__device__ __align__(16) float d_x0[NN * 64];
__device__ __align__(16) float d_bufA[NN * 128];
__device__ __align__(16) float d_bufB[NN * 128];
__device__ __align__(16) float d_bufC[NN * 128];
__device__ __align__(16) float d_dinv[NN];
__device__ int d_ecnt[NN];
__device__ int d_cursor[NN];
__device__ int d_rowptr[NN + 1];
__device__ int d_bsum[256];
__device__ int d_boff[256];
__device__ int d_csr_src[NE];
__device__ int d_csr_dst[NE];
__device__ __align__(16) float d_csr_norm[NE];
__device__ __align__(16) float d_gmax[NG * 128];
__device__ __align__(16) float d_gsum[NG * 128];
__device__ float d_gcnt[NG];
__device__ __align__(16) float d_g[NG * 256];
__device__ __align__(16) float d_h1[NG * 256];
__device__ __align__(16) __nv_bfloat16 d_Whi[128 * 136];
__device__ __align__(16) __nv_bfloat16 d_Wlo[128 * 136];
__device__ __align__(16) __nv_bfloat16 d_gWhi[5 * 128 * 136];
__device__ __align__(16) __nv_bfloat16 d_gWlo[5 * 128 * 136];

#define WIMG (128 * 136)

// ---------------- mma.sync helpers ----------------
__device__ __forceinline__ uint32_t smem_u32(const void* p) {
    uint32_t a;
    asm("{ .reg .u64 t; cvta.to.shared.u64 t, %1; cvt.u32.u64 %0, t; }" : "=r"(a) : "l"(p));
    return a;
}
__device__ __forceinline__ void ldm_x4(uint32_t* r, uint32_t addr) {
    asm volatile("ldmatrix.sync.aligned.m8n8.x4.shared.b16 {%0,%1,%2,%3}, [%4];"
                 : "=r"(r[0]), "=r"(r[1]), "=r"(r[2]), "=r"(r[3]) : "r"(addr));
}
__device__ __forceinline__ void mma16816(float* d, const uint32_t* a, const uint32_t* b) {
    asm volatile("mma.sync.aligned.m16n8k16.row.col.f32.bf16.bf16.f32 "
                 "{%0,%1,%2,%3}, {%4,%5,%6,%7}, {%8,%9}, {%0,%1,%2,%3};"
                 : "+f"(d[0]), "+f"(d[1]), "+f"(d[2]), "+f"(d[3])
                 : "r"(a[0]), "r"(a[1]), "r"(a[2]), "r"(a[3]), "r"(b[0]), "r"(b[1]));
}
__device__ __forceinline__ void split_pack(float v0, float v1, uint32_t& hi, uint32_t& lo) {
    __nv_bfloat16 h0 = __float2bfloat16(v0), h1 = __float2bfloat16(v1);
    __nv_bfloat16 l0 = __float2bfloat16(v0 - __bfloat162float(h0));
    __nv_bfloat16 l1 = __float2bfloat16(v1 - __bfloat162float(h1));
    hi = (uint32_t)__bfloat16_as_ushort(h0) | ((uint32_t)__bfloat16_as_ushort(h1) << 16);
    lo = (uint32_t)__bfloat16_as_ushort(l0) | ((uint32_t)__bfloat16_as_ushort(l1) << 16);
}

// ---------------- graph preprocessing ----------------
__global__ void k_init() {
    int i = blockIdx.x * blockDim.x + threadIdx.x;
    if (i < NN) { d_ecnt[i] = 0; d_cursor[i] = 0; }
}

__global__ void k_count(const int* __restrict__ dst) {
    int e = blockIdx.x * blockDim.x + threadIdx.x;
    if (e < NE) atomicAdd(&d_ecnt[dst[e]], 1);
}

// k_bsum + dinv fused
__global__ void k_bsum() {
    __shared__ int s[256];
    int t = threadIdx.x;
    int i = blockIdx.x * 256 + t;
    int c = (i < NN) ? d_ecnt[i] : 0;
    if (i < NN) d_dinv[i] = rsqrtf((float)c + 1.0f);
    s[t] = c;
    __syncthreads();
    #pragma unroll
    for (int off = 128; off > 0; off >>= 1) {
        if (t < off) s[t] += s[t + off];
        __syncthreads();
    }
    if (t == 0) d_bsum[blockIdx.x] = s[0];
}

__global__ void k_bscan() {
    __shared__ int s[256];
    int t = threadIdx.x;
    int v0 = (t < NB) ? d_bsum[t] : 0;
    s[t] = v0;
    __syncthreads();
    #pragma unroll
    for (int off = 1; off < 256; off <<= 1) {
        int v = (t >= off) ? s[t - off] : 0;
        __syncthreads();
        s[t] += v;
        __syncthreads();
    }
    d_boff[t] = s[t] - v0;
}

__global__ void k_escan() {
    __shared__ int s[256];
    int t = threadIdx.x;
    int i = blockIdx.x * 256 + t;
    int v0 = (i < NN) ? d_ecnt[i] : 0;
    s[t] = v0;
    __syncthreads();
    #pragma unroll
    for (int off = 1; off < 256; off <<= 1) {
        int v = (t >= off) ? s[t - off] : 0;
        __syncthreads();
        s[t] += v;
        __syncthreads();
    }
    if (i < NN) d_rowptr[i + 1] = d_boff[blockIdx.x] + s[t];
    if (i == 0) d_rowptr[0] = 0;
}

__global__ void k_scatter(const int* __restrict__ src, const int* __restrict__ dst) {
    int e = blockIdx.x * blockDim.x + threadIdx.x;
    if (e >= NE) return;
    int s = src[e], d = dst[e];
    int pos = d_rowptr[d] + atomicAdd(&d_cursor[d], 1);
    d_csr_src[pos] = s;
    d_csr_dst[pos] = d;
    d_csr_norm[pos] = d_dinv[s] * d_dinv[d];
}

// ---------------- x0 = [nodes | cat_emb[cats]] ----------------
__global__ void k_embed(const float* __restrict__ nodes, const int* __restrict__ cats,
                        const float* __restrict__ emb) {
    int t = blockIdx.x * blockDim.x + threadIdx.x;
    if (t >= NN * 16) return;
    int node = t >> 4, j = t & 15;
    float4 v;
    if (j < 8) v = ((const float4*)nodes)[node * 8 + j];
    else       v = ((const float4*)emb)[(size_t)cats[node] * 8 + (j - 8)];
    ((float4*)d_x0)[node * 16 + j] = v;
}

// ---------------- prebuild We2^T hi/lo image + zero pool accumulators ----------------
__global__ void k_prepw(const float* __restrict__ We2) {
    int i = blockIdx.x * blockDim.x + threadIdx.x;
    if (i < NG * 128) { d_gmax[i] = 0.f; d_gsum[i] = 0.f; }
    if (i < NG) d_gcnt[i] = 0.f;
    if (i >= 16384) return;
    int n = i >> 7, k = i & 127;
    float w = We2[k * 128 + n];
    __nv_bfloat16 h = __float2bfloat16(w);
    __nv_bfloat16 l = __float2bfloat16(w - __bfloat162float(h));
    d_Whi[n * 136 + k] = h;
    d_Wlo[n * 136 + k] = l;
}

// ---------------- prebuild node-GEMM weight images ----------------
__global__ void k_prepw_gen(const float* __restrict__ W1, const float* __restrict__ W2,
                            const float* __restrict__ W3, const float* __restrict__ We1) {
    int i = blockIdx.x * blockDim.x + threadIdx.x;
    if (i >= 5 * 16384) return;
    int img = i >> 14;
    int idx = i & 16383;
    int n = idx >> 7, k = idx & 127;
    float w;
    if (img == 0) {
        if (k >= 64) return;
        w = W1[k * 128 + n];
    } else if (img == 1) {
        w = W2[k * 128 + n];
    } else if (img == 2) {
        w = W3[k * 128 + n];
    } else if (img == 3) {
        w = We1[k * 128 + n] - We1[(k + 128) * 128 + n];
    } else {
        w = We1[(k + 128) * 128 + n];
    }
    __nv_bfloat16 h = __float2bfloat16(w);
    __nv_bfloat16 l = __float2bfloat16(w - __bfloat162float(h));
    d_gWhi[img * WIMG + n * 136 + k] = h;
    d_gWlo[img * WIMG + n * 136 + k] = l;
}

// shared smem layout for 64-row MMA blocks
#define XHI 0u
#define XLO 17408u
#define WHI 34816u
#define WLO 69632u
#define MMA_SMEM 104448

// ---------------- node GEMM via mma.sync bf16 3-split ----------------
__global__ void __launch_bounds__(256, 2)
gemm_mma(const float* __restrict__ X, int M, int Kin,
         const __nv_bfloat16* __restrict__ gWhi, const __nv_bfloat16* __restrict__ gWlo,
         const float* __restrict__ bias, int doRelu, float* __restrict__ Y) {
    extern __shared__ __align__(16) char smc[];
    const int t = threadIdx.x;
    const int wid = t >> 5;
    const int lane = t & 31;
    const int row0 = blockIdx.x * 64;
    const uint32_t sb = smem_u32(smc);

    {
        const uint4* gh = (const uint4*)gWhi;
        const uint4* gl = (const uint4*)gWlo;
        for (int i = t; i < 2176; i += 256) {
            asm volatile("cp.async.cg.shared.global [%0], [%1], 16;"
                         :: "r"(sb + WHI + i * 16), "l"(gh + i));
            asm volatile("cp.async.cg.shared.global [%0], [%1], 16;"
                         :: "r"(sb + WLO + i * 16), "l"(gl + i));
        }
        asm volatile("cp.async.commit_group;");
    }

    {
        int r = t & 63, hf = t >> 6;
        int gr = row0 + r;
        const float4* Xr = (const float4*)(X + (size_t)gr * Kin);
        int q = Kin >> 4;
        char* pHi = smc + XHI;
        char* pLo = smc + XLO;
        uint32_t rowb = (uint32_t)r * 272u;
        if (gr < M) {
            #pragma unroll 4
            for (int s = hf * q; s < (hf + 1) * q; ++s) {
                float4 v = __ldg(Xr + s);
                uint2 hv, lv;
                split_pack(v.x, v.y, hv.x, lv.x);
                split_pack(v.z, v.w, hv.y, lv.y);
                uint32_t off = rowb + (uint32_t)s * 8u;
                *(uint2*)(pHi + off) = hv;
                *(uint2*)(pLo + off) = lv;
            }
        } else {
            for (int s = hf * q; s < (hf + 1) * q; ++s) {
                uint32_t off = rowb + (uint32_t)s * 8u;
                *(uint2*)(pHi + off) = make_uint2(0u, 0u);
                *(uint2*)(pLo + off) = make_uint2(0u, 0u);
            }
        }
    }
    asm volatile("cp.async.wait_group 0;" ::: "memory");
    __syncthreads();

    const int wm = (wid & 1) * 32;
    const int wn = (wid >> 1) * 32;
    const int lid8 = lane & 7;
    const int grp = lane >> 3;

    uint32_t aAddrHi[2], aAddrLo[2];
    {
        uint32_t row = (uint32_t)(wm + (grp & 1) * 8 + lid8);
        uint32_t col = (uint32_t)((grp >> 1) * 8);
        #pragma unroll
        for (int mt = 0; mt < 2; ++mt) {
            uint32_t byteOff = (row + mt * 16) * 272u + col * 2u;
            aAddrHi[mt] = sb + XHI + byteOff;
            aAddrLo[mt] = sb + XLO + byteOff;
        }
    }
    uint32_t bAddrHi[2], bAddrLo[2];
    {
        uint32_t row = (uint32_t)(wn + (grp >> 1) * 8 + lid8);
        uint32_t col = (uint32_t)((grp & 1) * 8);
        #pragma unroll
        for (int p = 0; p < 2; ++p) {
            uint32_t byteOff = (row + p * 16) * 272u + col * 2u;
            bAddrHi[p] = sb + WHI + byteOff;
            bAddrLo[p] = sb + WLO + byteOff;
        }
    }

    float ac[2][4][4];
    #pragma unroll
    for (int i = 0; i < 2; i++)
        #pragma unroll
        for (int j = 0; j < 4; j++)
            #pragma unroll
            for (int q2 = 0; q2 < 4; q2++) ac[i][j][q2] = 0.f;

    const int nkt = Kin >> 4;
    for (int kt = 0; kt < nkt; ++kt) {
        uint32_t kb = kt * 32u;
        uint32_t aHi[2][4], aLo[2][4];
        uint32_t bHi[4][2], bLo[4][2];
        #pragma unroll
        for (int mt = 0; mt < 2; ++mt) {
            ldm_x4(aHi[mt], aAddrHi[mt] + kb);
            ldm_x4(aLo[mt], aAddrLo[mt] + kb);
        }
        #pragma unroll
        for (int p = 0; p < 2; ++p) {
            uint32_t r[4];
            ldm_x4(r, bAddrHi[p] + kb);
            bHi[2 * p][0] = r[0]; bHi[2 * p][1] = r[1];
            bHi[2 * p + 1][0] = r[2]; bHi[2 * p + 1][1] = r[3];
            ldm_x4(r, bAddrLo[p] + kb);
            bLo[2 * p][0] = r[0]; bLo[2 * p][1] = r[1];
            bLo[2 * p + 1][0] = r[2]; bLo[2 * p + 1][1] = r[3];
        }
        #pragma unroll
        for (int mt = 0; mt < 2; ++mt)
            #pragma unroll
            for (int nt = 0; nt < 4; ++nt) {
                mma16816(ac[mt][nt], aHi[mt], bHi[nt]);
                mma16816(ac[mt][nt], aHi[mt], bLo[nt]);
                mma16816(ac[mt][nt], aLo[mt], bHi[nt]);
            }
    }

    {
        int rr = lane >> 2;
        int cc = (lane & 3) * 2;
        #pragma unroll
        for (int nt = 0; nt < 4; ++nt) {
            int c = wn + nt * 8 + cc;
            float b0 = bias ? __ldg(bias + c)     : 0.f;
            float b1 = bias ? __ldg(bias + c + 1) : 0.f;
            #pragma unroll
            for (int mt = 0; mt < 2; ++mt) {
                int r0 = wm + mt * 16 + rr;
                int gr0 = row0 + r0;
                int gr1 = gr0 + 8;
                float o00 = ac[mt][nt][0] + b0, o01 = ac[mt][nt][1] + b1;
                float o10 = ac[mt][nt][2] + b0, o11 = ac[mt][nt][3] + b1;
                if (doRelu) {
                    o00 = fmaxf(o00, 0.f); o01 = fmaxf(o01, 0.f);
                    o10 = fmaxf(o10, 0.f); o11 = fmaxf(o11, 0.f);
                }
                if (gr0 < M)
                    *(float2*)&Y[(size_t)gr0 * 128 + c] = make_float2(o00, o01);
                if (gr1 < M)
                    *(float2*)&Y[(size_t)gr1 * 128 + c] = make_float2(o10, o11);
            }
        }
    }
}

// ---------------- fused dual GEMM (EdgeConv precompute): A = X@Wd + be1; B = X@Wb ----------------
// Also ZEROES its X tile rows (X = bufC becomes the edge-agg output buffer).
__global__ void __launch_bounds__(256, 2)
gemm_mma_dual(float* __restrict__ X, int M,
              const __nv_bfloat16* __restrict__ WdHi, const __nv_bfloat16* __restrict__ WdLo,
              const __nv_bfloat16* __restrict__ WbHi, const __nv_bfloat16* __restrict__ WbLo,
              const float* __restrict__ be1,
              float* __restrict__ Aout, float* __restrict__ Bout) {
    extern __shared__ __align__(16) char smc[];
    const int t = threadIdx.x;
    const int wid = t >> 5;
    const int lane = t & 31;
    const int row0 = blockIdx.x * 64;
    const uint32_t sb = smem_u32(smc);

    {
        const uint4* gh = (const uint4*)WdHi;
        const uint4* gl = (const uint4*)WdLo;
        for (int i = t; i < 2176; i += 256) {
            asm volatile("cp.async.cg.shared.global [%0], [%1], 16;"
                         :: "r"(sb + WHI + i * 16), "l"(gh + i));
            asm volatile("cp.async.cg.shared.global [%0], [%1], 16;"
                         :: "r"(sb + WLO + i * 16), "l"(gl + i));
        }
        asm volatile("cp.async.commit_group;");
    }

    // gather X rows once; then zero the rows in place (bufC reused as edge-agg output)
    {
        int r = t & 63, hf = t >> 6;
        int gr = row0 + r;
        float4* Xr = (float4*)(X + (size_t)gr * 128);
        char* pHi = smc + XHI;
        char* pLo = smc + XLO;
        uint32_t rowb = (uint32_t)r * 272u;
        if (gr < M) {
            #pragma unroll 8
            for (int s = hf * 8; s < hf * 8 + 8; ++s) {
                float4 v = __ldg((const float4*)Xr + s);
                uint2 hv, lv;
                split_pack(v.x, v.y, hv.x, lv.x);
                split_pack(v.z, v.w, hv.y, lv.y);
                uint32_t off = rowb + (uint32_t)s * 8u;
                *(uint2*)(pHi + off) = hv;
                *(uint2*)(pLo + off) = lv;
                Xr[s] = make_float4(0.f, 0.f, 0.f, 0.f);
            }
        } else {
            for (int s = hf * 8; s < hf * 8 + 8; ++s) {
                uint32_t off = rowb + (uint32_t)s * 8u;
                *(uint2*)(pHi + off) = make_uint2(0u, 0u);
                *(uint2*)(pLo + off) = make_uint2(0u, 0u);
            }
        }
    }
    asm volatile("cp.async.wait_group 0;" ::: "memory");
    __syncthreads();

    const int wm = (wid & 1) * 32;
    const int wn = (wid >> 1) * 32;
    const int lid8 = lane & 7;
    const int grp = lane >> 3;

    uint32_t aAddrHi[2], aAddrLo[2];
    {
        uint32_t row = (uint32_t)(wm + (grp & 1) * 8 + lid8);
        uint32_t col = (uint32_t)((grp >> 1) * 8);
        #pragma unroll
        for (int mt = 0; mt < 2; ++mt) {
            uint32_t byteOff = (row + mt * 16) * 272u + col * 2u;
            aAddrHi[mt] = sb + XHI + byteOff;
            aAddrLo[mt] = sb + XLO + byteOff;
        }
    }
    uint32_t bAddrHi[2], bAddrLo[2];
    {
        uint32_t row = (uint32_t)(wn + (grp >> 1) * 8 + lid8);
        uint32_t col = (uint32_t)((grp & 1) * 8);
        #pragma unroll
        for (int p = 0; p < 2; ++p) {
            uint32_t byteOff = (row + p * 16) * 272u + col * 2u;
            bAddrHi[p] = sb + WHI + byteOff;
            bAddrLo[p] = sb + WLO + byteOff;
        }
    }

    const int rr = lane >> 2;
    const int cc = (lane & 3) * 2;

    #pragma unroll 1
    for (int pass = 0; pass < 2; ++pass) {
        float ac[2][4][4];
        #pragma unroll
        for (int i = 0; i < 2; i++)
            #pragma unroll
            for (int j = 0; j < 4; j++)
                #pragma unroll
                for (int q2 = 0; q2 < 4; q2++) ac[i][j][q2] = 0.f;

        #pragma unroll
        for (int kt = 0; kt < 8; ++kt) {
            uint32_t kb = kt * 32u;
            uint32_t aHi[2][4], aLo[2][4];
            uint32_t bHi[4][2], bLo[4][2];
            #pragma unroll
            for (int mt = 0; mt < 2; ++mt) {
                ldm_x4(aHi[mt], aAddrHi[mt] + kb);
                ldm_x4(aLo[mt], aAddrLo[mt] + kb);
            }
            #pragma unroll
            for (int p = 0; p < 2; ++p) {
                uint32_t r[4];
                ldm_x4(r, bAddrHi[p] + kb);
                bHi[2 * p][0] = r[0]; bHi[2 * p][1] = r[1];
                bHi[2 * p + 1][0] = r[2]; bHi[2 * p + 1][1] = r[3];
                ldm_x4(r, bAddrLo[p] + kb);
                bLo[2 * p][0] = r[0]; bLo[2 * p][1] = r[1];
                bLo[2 * p + 1][0] = r[2]; bLo[2 * p + 1][1] = r[3];
            }
            #pragma unroll
            for (int mt = 0; mt < 2; ++mt)
                #pragma unroll
                for (int nt = 0; nt < 4; ++nt) {
                    mma16816(ac[mt][nt], aHi[mt], bHi[nt]);
                    mma16816(ac[mt][nt], aHi[mt], bLo[nt]);
                    mma16816(ac[mt][nt], aLo[mt], bHi[nt]);
                }
        }

        if (pass == 0) {
            __syncthreads();
            {
                const uint4* gh = (const uint4*)WbHi;
                const uint4* gl = (const uint4*)WbLo;
                for (int i = t; i < 2176; i += 256) {
                    asm volatile("cp.async.cg.shared.global [%0], [%1], 16;"
                                 :: "r"(sb + WHI + i * 16), "l"(gh + i));
                    asm volatile("cp.async.cg.shared.global [%0], [%1], 16;"
                                 :: "r"(sb + WLO + i * 16), "l"(gl + i));
                }
                asm volatile("cp.async.commit_group;");
            }
            #pragma unroll
            for (int nt = 0; nt < 4; ++nt) {
                int c = wn + nt * 8 + cc;
                float b0 = __ldg(be1 + c);
                float b1 = __ldg(be1 + c + 1);
                #pragma unroll
                for (int mt = 0; mt < 2; ++mt) {
                    int r0 = wm + mt * 16 + rr;
                    int gr0 = row0 + r0;
                    int gr1 = gr0 + 8;
                    if (gr0 < M)
                        *(float2*)&Aout[(size_t)gr0 * 128 + c] =
                            make_float2(ac[mt][nt][0] + b0, ac[mt][nt][1] + b1);
                    if (gr1 < M)
                        *(float2*)&Aout[(size_t)gr1 * 128 + c] =
                            make_float2(ac[mt][nt][2] + b0, ac[mt][nt][3] + b1);
                }
            }
            asm volatile("cp.async.wait_group 0;" ::: "memory");
            __syncthreads();
        } else {
            #pragma unroll
            for (int nt = 0; nt < 4; ++nt) {
                int c = wn + nt * 8 + cc;
                #pragma unroll
                for (int mt = 0; mt < 2; ++mt) {
                    int r0 = wm + mt * 16 + rr;
                    int gr0 = row0 + r0;
                    int gr1 = gr0 + 8;
                    if (gr0 < M)
                        *(float2*)&Bout[(size_t)gr0 * 128 + c] =
                            make_float2(ac[mt][nt][0], ac[mt][nt][1]);
                    if (gr1 < M)
                        *(float2*)&Bout[(size_t)gr1 * 128 + c] =
                            make_float2(ac[mt][nt][2], ac[mt][nt][3]);
                }
            }
        }
    }
}

// ---------------- GCN aggregation (128 cols, bias+relu) ----------------
__global__ void gcn_agg(const float* __restrict__ H, const float* __restrict__ bias,
                        float* __restrict__ out) {
    int warp = threadIdx.x >> 5;
    int lane = threadIdx.x & 31;
    int node = blockIdx.x * 8 + warp;
    if (node >= NN) return;
    float dv = d_dinv[node];
    float sn = dv * dv;
    float4 acc = ((const float4*)H)[node * 32 + lane];
    acc.x *= sn; acc.y *= sn; acc.z *= sn; acc.w *= sn;
    int beg = d_rowptr[node], end = d_rowptr[node + 1];
    int e = beg;
    for (; e + 3 < end; e += 4) {
        int s0 = d_csr_src[e],     s1 = d_csr_src[e + 1];
        int s2 = d_csr_src[e + 2], s3 = d_csr_src[e + 3];
        float n0 = d_csr_norm[e],     n1 = d_csr_norm[e + 1];
        float n2 = d_csr_norm[e + 2], n3 = d_csr_norm[e + 3];
        float4 h0 = ((const float4*)H)[s0 * 32 + lane];
        float4 h1 = ((const float4*)H)[s1 * 32 + lane];
        float4 h2 = ((const float4*)H)[s2 * 32 + lane];
        float4 h3 = ((const float4*)H)[s3 * 32 + lane];
        acc.x = fmaf(h0.x, n0, acc.x); acc.y = fmaf(h0.y, n0, acc.y);
        acc.z = fmaf(h0.z, n0, acc.z); acc.w = fmaf(h0.w, n0, acc.w);
        acc.x = fmaf(h1.x, n1, acc.x); acc.y = fmaf(h1.y, n1, acc.y);
        acc.z = fmaf(h1.z, n1, acc.z); acc.w = fmaf(h1.w, n1, acc.w);
        acc.x = fmaf(h2.x, n2, acc.x); acc.y = fmaf(h2.y, n2, acc.y);
        acc.z = fmaf(h2.z, n2, acc.z); acc.w = fmaf(h2.w, n2, acc.w);
        acc.x = fmaf(h3.x, n3, acc.x); acc.y = fmaf(h3.y, n3, acc.y);
        acc.z = fmaf(h3.z, n3, acc.z); acc.w = fmaf(h3.w, n3, acc.w);
    }
    for (; e < end; ++e) {
        int s = d_csr_src[e];
        float nm = d_csr_norm[e];
        float4 h = ((const float4*)H)[s * 32 + lane];
        acc.x = fmaf(h.x, nm, acc.x); acc.y = fmaf(h.y, nm, acc.y);
        acc.z = fmaf(h.z, nm, acc.z); acc.w = fmaf(h.w, nm, acc.w);
    }
    float4 b = ((const float4*)bias)[lane];
    float4 r;
    r.x = fmaxf(acc.x + b.x, 0.f);
    r.y = fmaxf(acc.y + b.y, 0.f);
    r.z = fmaxf(acc.z + b.z, 0.f);
    r.w = fmaxf(acc.w + b.w, 0.f);
    ((float4*)out)[node * 32 + lane] = r;
}

// ---------------- GCN aggregation, 64 cols (layer-1 pre-agg) ----------------
__global__ void gcn_agg64(const float* __restrict__ H, float* __restrict__ out) {
    int t = threadIdx.x;
    int half = t >> 4;
    int li = t & 15;
    int node = blockIdx.x * 16 + half;
    if (node >= NN) return;
    float dv = d_dinv[node];
    float sn = dv * dv;
    float4 acc = ((const float4*)H)[node * 16 + li];
    acc.x *= sn; acc.y *= sn; acc.z *= sn; acc.w *= sn;
    int beg = d_rowptr[node], end = d_rowptr[node + 1];
    int e = beg;
    for (; e + 3 < end; e += 4) {
        int s0 = d_csr_src[e],     s1 = d_csr_src[e + 1];
        int s2 = d_csr_src[e + 2], s3 = d_csr_src[e + 3];
        float n0 = d_csr_norm[e],     n1 = d_csr_norm[e + 1];
        float n2 = d_csr_norm[e + 2], n3 = d_csr_norm[e + 3];
        float4 h0 = ((const float4*)H)[s0 * 16 + li];
        float4 h1 = ((const float4*)H)[s1 * 16 + li];
        float4 h2 = ((const float4*)H)[s2 * 16 + li];
        float4 h3 = ((const float4*)H)[s3 * 16 + li];
        acc.x = fmaf(h0.x, n0, acc.x); acc.y = fmaf(h0.y, n0, acc.y);
        acc.z = fmaf(h0.z, n0, acc.z); acc.w = fmaf(h0.w, n0, acc.w);
        acc.x = fmaf(h1.x, n1, acc.x); acc.y = fmaf(h1.y, n1, acc.y);
        acc.z = fmaf(h1.z, n1, acc.z); acc.w = fmaf(h1.w, n1, acc.w);
        acc.x = fmaf(h2.x, n2, acc.x); acc.y = fmaf(h2.y, n2, acc.y);
        acc.z = fmaf(h2.z, n2, acc.z); acc.w = fmaf(h2.w, n2, acc.w);
        acc.x = fmaf(h3.x, n3, acc.x); acc.y = fmaf(h3.y, n3, acc.y);
        acc.z = fmaf(h3.z, n3, acc.z); acc.w = fmaf(h3.w, n3, acc.w);
    }
    for (; e < end; ++e) {
        int s = d_csr_src[e];
        float nm = d_csr_norm[e];
        float4 h = ((const float4*)H)[s * 16 + li];
        acc.x = fmaf(h.x, nm, acc.x); acc.y = fmaf(h.y, nm, acc.y);
        acc.z = fmaf(h.z, nm, acc.z); acc.w = fmaf(h.w, nm, acc.w);
    }
    ((float4*)out)[node * 16 + li] = acc;
}

// ---------------- EdgeConv via mma.sync bf16 3-MMA split ----------------
// 64 edges/block, 256 threads, 2 CTAs/SM.
__global__ void __launch_bounds__(256, 2)
edge_mlp_mma(const float* __restrict__ A, const float* __restrict__ Bm,
             const float* __restrict__ be2, float* __restrict__ agg) {
    extern __shared__ __align__(16) char smc[];
    __shared__ int sDst[64];
    __shared__ int sSrc[64];

    const int t = threadIdx.x;
    const int wid = t >> 5;
    const int lane = t & 31;
    const int e0 = blockIdx.x * 64;
    const uint32_t sb = smem_u32(smc);

    if (t < 64) { sDst[t] = d_csr_dst[e0 + t]; sSrc[t] = d_csr_src[e0 + t]; }

    {
        const uint4* gh = (const uint4*)d_Whi;
        const uint4* gl = (const uint4*)d_Wlo;
        for (int i = t; i < 2176; i += 256) {
            asm volatile("cp.async.cg.shared.global [%0], [%1], 16;"
                         :: "r"(sb + WHI + i * 16), "l"(gh + i));
            asm volatile("cp.async.cg.shared.global [%0], [%1], 16;"
                         :: "r"(sb + WLO + i * 16), "l"(gl + i));
        }
        asm volatile("cp.async.commit_group;");
    }
    __syncthreads();

    {
        int e = t & 63, hf = t >> 6;
        int d = sDst[e], s = sSrc[e];
        const float4* Ad = (const float4*)(A  + (size_t)d * 128);
        const float4* Bs = (const float4*)(Bm + (size_t)s * 128);
        uint32_t rowb = (uint32_t)e * 272u;
        char* pHi = smc + XHI;
        char* pLo = smc + XLO;
        #pragma unroll 8
        for (int seg = hf * 8; seg < hf * 8 + 8; ++seg) {
            float4 av = __ldg(Ad + seg);
            float4 bv = __ldg(Bs + seg);
            float v0 = fmaxf(av.x + bv.x, 0.f);
            float v1 = fmaxf(av.y + bv.y, 0.f);
            float v2 = fmaxf(av.z + bv.z, 0.f);
            float v3 = fmaxf(av.w + bv.w, 0.f);
            uint2 hv, lv;
            split_pack(v0, v1, hv.x, lv.x);
            split_pack(v2, v3, hv.y, lv.y);
            uint32_t off = rowb + (uint32_t)seg * 8u;
            *(uint2*)(pHi + off) = hv;
            *(uint2*)(pLo + off) = lv;
        }
    }
    asm volatile("cp.async.wait_group 0;" ::: "memory");
    __syncthreads();

    const int wm = (wid & 1) * 32;
    const int wn = (wid >> 1) * 32;
    const int lid8 = lane & 7;
    const int grp = lane >> 3;

    uint32_t aAddrHi[2], aAddrLo[2];
    {
        uint32_t row = (uint32_t)(wm + (grp & 1) * 8 + lid8);
        uint32_t col = (uint32_t)((grp >> 1) * 8);
        #pragma unroll
        for (int mt = 0; mt < 2; ++mt) {
            uint32_t byteOff = (row + mt * 16) * 272u + col * 2u;
            aAddrHi[mt] = sb + XHI + byteOff;
            aAddrLo[mt] = sb + XLO + byteOff;
        }
    }
    uint32_t bAddrHi[2], bAddrLo[2];
    {
        uint32_t row = (uint32_t)(wn + (grp >> 1) * 8 + lid8);
        uint32_t col = (uint32_t)((grp & 1) * 8);
        #pragma unroll
        for (int p = 0; p < 2; ++p) {
            uint32_t byteOff = (row + p * 16) * 272u + col * 2u;
            bAddrHi[p] = sb + WHI + byteOff;
            bAddrLo[p] = sb + WLO + byteOff;
        }
    }

    float ac[2][4][4];
    #pragma unroll
    for (int i = 0; i < 2; i++)
        #pragma unroll
        for (int j = 0; j < 4; j++)
            #pragma unroll
            for (int q2 = 0; q2 < 4; q2++) ac[i][j][q2] = 0.f;

    #pragma unroll
    for (int kt = 0; kt < 8; ++kt) {
        uint32_t kb = kt * 32u;
        uint32_t aHi[2][4], aLo[2][4];
        uint32_t bHi[4][2], bLo[4][2];
        #pragma unroll
        for (int mt = 0; mt < 2; ++mt) {
            ldm_x4(aHi[mt], aAddrHi[mt] + kb);
            ldm_x4(aLo[mt], aAddrLo[mt] + kb);
        }
        #pragma unroll
        for (int p = 0; p < 2; ++p) {
            uint32_t r[4];
            ldm_x4(r, bAddrHi[p] + kb);
            bHi[2 * p][0] = r[0]; bHi[2 * p][1] = r[1];
            bHi[2 * p + 1][0] = r[2]; bHi[2 * p + 1][1] = r[3];
            ldm_x4(r, bAddrLo[p] + kb);
            bLo[2 * p][0] = r[0]; bLo[2 * p][1] = r[1];
            bLo[2 * p + 1][0] = r[2]; bLo[2 * p + 1][1] = r[3];
        }
        #pragma unroll
        for (int mt = 0; mt < 2; ++mt)
            #pragma unroll
            for (int nt = 0; nt < 4; ++nt) {
                mma16816(ac[mt][nt], aHi[mt], bHi[nt]);
                mma16816(ac[mt][nt], aHi[mt], bLo[nt]);
                mma16816(ac[mt][nt], aLo[mt], bHi[nt]);
            }
    }
    __syncthreads();

    float* sR = (float*)smc;
    {
        int rr = lane >> 2;
        int cc = (lane & 3) * 2;
        #pragma unroll
        for (int mt = 0; mt < 2; ++mt)
            #pragma unroll
            for (int nt = 0; nt < 4; ++nt) {
                int r0 = wm + mt * 16 + rr;
                int c = wn + nt * 8 + cc;
                *(float2*)&sR[r0 * 130 + c]       = make_float2(ac[mt][nt][0], ac[mt][nt][1]);
                *(float2*)&sR[(r0 + 8) * 130 + c] = make_float2(ac[mt][nt][2], ac[mt][nt][3]);
            }
    }
    __syncthreads();

    {
        int col = t >> 1;
        int q = t & 1;
        int eb = q * 32;
        float bias = __ldg(be2 + col);
        int cur = sDst[eb];
        float m = sR[eb * 130 + col];
        #pragma unroll 4
        for (int i = 1; i < 32; ++i) {
            int e = eb + i;
            int d = sDst[e];
            float v = sR[e * 130 + col];
            if (d != cur) {
                float mb = m + bias;
                if (mb > 0.f) atomicMax((int*)(agg + (size_t)cur * 128 + col), __float_as_int(mb));
                cur = d; m = v;
            } else {
                m = fmaxf(m, v);
            }
        }
        float mb = m + bias;
        if (mb > 0.f) atomicMax((int*)(agg + (size_t)cur * 128 + col), __float_as_int(mb));
    }
}

// ---------------- pooling ----------------
__global__ void __launch_bounds__(256)
k_pool2(const int* __restrict__ batch, const float* __restrict__ X) {
    int base = blockIdx.x * 128;
    int ch = threadIdx.x & 127;
    int half = threadIdx.x >> 7;
    int cur = -1;
    float vmax = 0.f, vsum = 0.f;
    for (int i = half; i < 128; i += 2) {
        int n = base + i;
        if (n >= NN) break;
        int g = batch[n];
        if (g != cur) {
            if (cur >= 0) {
                atomicAdd(&d_gsum[cur * 128 + ch], vsum);
                if (vmax > 0.f) atomicMax((int*)&d_gmax[cur * 128 + ch], __float_as_int(vmax));
            }
            cur = g; vmax = 0.f; vsum = 0.f;
        }
        float v = X[(size_t)n * 128 + ch];
        vsum += v;
        vmax = fmaxf(vmax, v);
    }
    if (cur >= 0) {
        atomicAdd(&d_gsum[cur * 128 + ch], vsum);
        if (vmax > 0.f) atomicMax((int*)&d_gmax[cur * 128 + ch], __float_as_int(vmax));
    }
    if (threadIdx.x == 0) {
        int c = -1; float cnt = 0.f;
        for (int i = 0; i < 128; ++i) {
            int n = base + i;
            if (n >= NN) break;
            int g = batch[n];
            if (g != c) {
                if (c >= 0) atomicAdd(&d_gcnt[c], cnt);
                c = g; cnt = 0.f;
            }
            cnt += 1.f;
        }
        if (c >= 0) atomicAdd(&d_gcnt[c], cnt);
    }
}

__global__ void k_pool_fin() {
    int t = blockIdx.x * blockDim.x + threadIdx.x;
    if (t >= NG * 256) return;
    int g = t >> 8, c = t & 255;
    float v;
    if (c < 128) v = d_gmax[g * 128 + c];
    else         v = d_gsum[g * 128 + c - 128] / fmaxf(d_gcnt[g], 1.0f);
    d_g[t] = v;
}

// ---------------- head ----------------
__global__ void head_gemm(const float* __restrict__ in, const float* __restrict__ W,
                          const float* __restrict__ b, float* __restrict__ out) {
    __shared__ float srow[256];
    int t = threadIdx.x;
    int g = blockIdx.x;
    srow[t] = in[g * 256 + t];
    __syncthreads();
    float acc = b[t];
    #pragma unroll 8
    for (int k = 0; k < 256; ++k) acc = fmaf(srow[k], W[k * 256 + t], acc);
    out[g * 256 + t] = fmaxf(acc, 0.f);
}

// ---------------- launch ----------------
extern "C" void kernel_launch(void* const* d_in, const int* in_sizes, int n_in,
                              void* d_out, int out_size) {
    const float* nodes   = (const float*)d_in[0];
    const int*   cats    = (const int*)d_in[1];
    const int*   ei      = (const int*)d_in[2];
    const int*   batch   = (const int*)d_in[3];
    const float* cat_emb = (const float*)d_in[4];
    const float* W1  = (const float*)d_in[5];
    const float* b1  = (const float*)d_in[6];
    const float* W2  = (const float*)d_in[7];
    const float* b2  = (const float*)d_in[8];
    const float* W3  = (const float*)d_in[9];
    const float* b3  = (const float*)d_in[10];
    const float* We1 = (const float*)d_in[11];
    const float* be1 = (const float*)d_in[12];
    const float* We2 = (const float*)d_in[13];
    const float* be2 = (const float*)d_in[14];
    const float* Wf1 = (const float*)d_in[15];
    const float* bf1 = (const float*)d_in[16];
    const float* Wf2 = (const float*)d_in[17];
    const float* bf2 = (const float*)d_in[18];
    const int* src = ei;
    const int* dst = ei + NE;
    float* out = (float*)d_out;

    cudaFuncSetAttribute(gemm_mma,      cudaFuncAttributeMaxDynamicSharedMemorySize, MMA_SMEM);
    cudaFuncSetAttribute(gemm_mma_dual, cudaFuncAttributeMaxDynamicSharedMemorySize, MMA_SMEM);
    cudaFuncSetAttribute(edge_mlp_mma,  cudaFuncAttributeMaxDynamicSharedMemorySize, MMA_SMEM);

    float *bufA, *bufB, *bufC, *x0, *g, *h1;
    __nv_bfloat16 *gwh, *gwl;
    cudaGetSymbolAddress((void**)&bufA, d_bufA);
    cudaGetSymbolAddress((void**)&bufB, d_bufB);
    cudaGetSymbolAddress((void**)&bufC, d_bufC);
    cudaGetSymbolAddress((void**)&x0,   d_x0);
    cudaGetSymbolAddress((void**)&g,    d_g);
    cudaGetSymbolAddress((void**)&h1,   d_h1);
    cudaGetSymbolAddress((void**)&gwh,  d_gWhi);
    cudaGetSymbolAddress((void**)&gwl,  d_gWlo);

    // CSR + norms
    k_init<<<(NN + 255) / 256, 256>>>();
    k_count<<<(NE + 255) / 256, 256>>>(dst);
    k_bsum<<<NB, 256>>>();          // also computes dinv
    k_bscan<<<1, 256>>>();
    k_escan<<<NB, 256>>>();
    k_scatter<<<(NE + 255) / 256, 256>>>(src, dst);

    // x0 = [nodes | emb]; weight images (+ pool accumulator zeroing in k_prepw)
    k_embed<<<(NN * 16 + 255) / 256, 256>>>(nodes, cats, cat_emb);
    k_prepw<<<64, 256>>>(We2);
    k_prepw_gen<<<(5 * 16384 + 255) / 256, 256>>>(W1, W2, W3, We1);

    const int gg = (NN + 63) / 64;  // 782
    // GCN 1 (aggregate 64-dim x0 first, then GEMM with bias+relu)
    gcn_agg64<<<(NN + 15) / 16, 256>>>(x0, bufC);
    gemm_mma<<<gg, 256, MMA_SMEM>>>(bufC, NN, 64, gwh + 0 * WIMG, gwl + 0 * WIMG, b1, 1, bufB);
    // GCN 2
    gemm_mma<<<gg, 256, MMA_SMEM>>>(bufB, NN, 128, gwh + 1 * WIMG, gwl + 1 * WIMG, nullptr, 0, bufA);
    gcn_agg<<<(NN + 7) / 8, 256>>>(bufA, b2, bufB);
    // GCN 3
    gemm_mma<<<gg, 256, MMA_SMEM>>>(bufB, NN, 128, gwh + 2 * WIMG, gwl + 2 * WIMG, nullptr, 0, bufA);
    gcn_agg<<<(NN + 7) / 8, 256>>>(bufA, b3, bufC);   // x3 -> bufC

    // EdgeConv precompute (fused dual GEMM; also zeroes bufC): A = x3@Wd + be1 ; B = x3@Wb
    gemm_mma_dual<<<gg, 256, MMA_SMEM>>>(bufC, NN,
                                         gwh + 3 * WIMG, gwl + 3 * WIMG,
                                         gwh + 4 * WIMG, gwl + 4 * WIMG,
                                         be1, bufA, bufB);

    // EdgeConv per-edge MLP + segment max via mma.sync (bufC pre-zeroed by dual)
    edge_mlp_mma<<<NE / 64, 256, MMA_SMEM>>>(bufA, bufB, be2, bufC);

    // pooling (accumulators pre-zeroed in k_prepw)
    k_pool2<<<(NN + 127) / 128, 256>>>(batch, bufC);
    k_pool_fin<<<(NG * 256 + 255) / 256, 256>>>();

    // head
    head_gemm<<<NG, 256>>>(g, Wf1, bf1, h1);
    head_gemm<<<NG, 256>>>(h1, Wf2, bf2, out);
}